// round 11
// baseline (speedup 1.0000x reference)
#include <cuda_runtime.h>

#define DIM 256
#define PLANE (DIM*DIM)
#define NELEM (DIM*DIM*DIM)

#define HTILES 64          // h tiles of 4 rows (1 row per thread)
#define DCHUNKS 9
#define DPC 29             // 9*29 = 261 >= 254; one clean wave at occ 4
#define NBLOCKS (HTILES*DCHUNKS)   // 576

__device__ float g_partials[NBLOCKS];
__device__ unsigned int g_count = 0;   // wraps to 0 each launch via atomicInc

__device__ __forceinline__ float sqrt_approx(float x) {
    float r;
    asm("sqrt.approx.f32 %0, %1;" : "=f"(r) : "f"(x));
    return r;
}

__global__ __launch_bounds__(256, 4)
void grad_loss_fused(const float* __restrict__ x1,
                     const float* __restrict__ x2,
                     float* __restrict__ out) {
    __shared__ float ssum[8];
    __shared__ int s_last;

    const int tx = threadIdx.x;            // 0..63 -> w quad
    const int ty = threadIdx.y;            // 0..3  -> h row
    const int htile = blockIdx.x;          // 0..63
    const int chunk = blockIdx.y;          // 0..8
    const int bid = chunk * HTILES + htile;

    const int h  = 1 + htile * 4 + ty;     // 1..256
    const int w0 = tx * 4;
    const int d0 = 1 + chunk * DPC;
    const int niter = min(DIM - 2, d0 + DPC - 1) - d0 + 1;
    const int lane = tx & 31;

    const bool hcomp = (h <= DIM - 2);     // uniform per warp

    float local = 0.0f;

    if (hcomp) {
        const float wh  = (h == 1 || h == DIM - 2) ? 2.0f : 1.0f;
        const float wl  = (tx == 0)  ? 2.0f : 1.0f;
        const float wr  = (tx == 63) ? 2.0f : 1.0f;
        const bool  hasl = (tx > 0);
        const bool  hasr = (tx < 63);
        // Warp-boundary lanes that have a true left/right neighbor must load
        // the 1 scalar from memory; all other lanes get it via shfl. Block-edge
        // lanes (tx==0 / tx==63) keep a garbage value that only feeds the
        // discarded m00/m03 terms.
        const bool  ld_lf = (lane == 0)  && hasl;
        const bool  ld_rt = (lane == 31) && hasr;

        // q points at (d, h, w0); advance by PLANE per iteration.
        const float* q1 = x1 + d0 * PLANE + h * DIM + w0;
        const float* q2 = x2 + d0 * PLANE + h * DIM + w0;

        // Register window: A = d-1, B = d, C = d+1; D = d+2 prefetched.
        float4 A0 = *(const float4*)(q1 - PLANE);
        float4 A1 = *(const float4*)(q2 - PLANE);
        float4 B0 = *(const float4*)(q1);
        float4 B1 = *(const float4*)(q2);
        float4 C0 = *(const float4*)(q1 + PLANE);
        float4 C1 = *(const float4*)(q2 + PLANE);

        int d = d0;
        #pragma unroll 2
        for (int it = 0; it < niter; ++it, ++d, q1 += PLANE, q2 += PLANE) {
            // ---- prefetch plane d+2 (consumed NEXT iteration) ----
            const int pf = (d + 2 <= DIM - 1) ? 2 * PLANE : PLANE;
            const float4 D0 = *(const float4*)(q1 + pf);
            const float4 D1 = *(const float4*)(q2 + pf);

            // ---- cache-resident neighbor loads for this iteration ----
            const float4 up0 = *(const float4*)(q1 - DIM);
            const float4 dn0 = *(const float4*)(q1 + DIM);
            const float4 up1 = *(const float4*)(q2 - DIM);
            const float4 dn1 = *(const float4*)(q2 + DIM);

            // ---- w-neighbors from registers via shfl; 1-lane edge loads ----
            float lf0 = __shfl_up_sync(0xffffffffu, B0.w, 1);
            float rt0 = __shfl_down_sync(0xffffffffu, B0.x, 1);
            float lf1 = __shfl_up_sync(0xffffffffu, B1.w, 1);
            float rt1 = __shfl_down_sync(0xffffffffu, B1.x, 1);
            if (ld_lf) { lf0 = q1[-1]; lf1 = q2[-1]; }
            if (ld_rt) { rt0 = q1[4];  rt1 = q2[4]; }

            const float wd = (d == 1 || d == DIM - 2) ? 2.0f : 1.0f;

            float gw, gh, gd;
            float m00, m01, m02, m03;
            gw = B0.y - lf0;  gh = dn0.x - up0.x;  gd = C0.x - A0.x;
            m00 = sqrt_approx(gw*gw + gh*gh + gd*gd + 1e-6f);
            gw = B0.z - B0.x; gh = dn0.y - up0.y;  gd = C0.y - A0.y;
            m01 = sqrt_approx(gw*gw + gh*gh + gd*gd + 1e-6f);
            gw = B0.w - B0.y; gh = dn0.z - up0.z;  gd = C0.z - A0.z;
            m02 = sqrt_approx(gw*gw + gh*gh + gd*gd + 1e-6f);
            gw = rt0 - B0.z;  gh = dn0.w - up0.w;  gd = C0.w - A0.w;
            m03 = sqrt_approx(gw*gw + gh*gh + gd*gd + 1e-6f);

            float m10, m11, m12, m13;
            gw = B1.y - lf1;  gh = dn1.x - up1.x;  gd = C1.x - A1.x;
            m10 = sqrt_approx(gw*gw + gh*gh + gd*gd + 1e-6f);
            gw = B1.z - B1.x; gh = dn1.y - up1.y;  gd = C1.y - A1.y;
            m11 = sqrt_approx(gw*gw + gh*gh + gd*gd + 1e-6f);
            gw = B1.w - B1.y; gh = dn1.z - up1.z;  gd = C1.z - A1.z;
            m12 = sqrt_approx(gw*gw + gh*gh + gd*gd + 1e-6f);
            gw = rt1 - B1.z;  gh = dn1.w - up1.w;  gd = C1.w - A1.w;
            m13 = sqrt_approx(gw*gw + gh*gh + gd*gd + 1e-6f);

            float s = 0.0f;
            if (hasl) s += fabsf(m00 - m10);
            s += wl * fabsf(m01 - m11);
            s += wr * fabsf(m02 - m12);
            if (hasr) s += fabsf(m03 - m13);
            local += wd * wh * s;

            // rotate window forward (renamed away by unroll)
            A0 = B0; A1 = B1; B0 = C0; B1 = C1; C0 = D0; C1 = D1;
        }
    }

    // ---- block reduction ----
    #pragma unroll
    for (int off = 16; off > 0; off >>= 1)
        local += __shfl_xor_sync(0xffffffffu, local, off);

    const int tid  = ty * 64 + tx;
    const int warp = tid >> 5;
    if (lane == 0) ssum[warp] = local;
    __syncthreads();

    if (tid == 0) {
        float v = 0.0f;
        #pragma unroll
        for (int i = 0; i < 8; ++i) v += ssum[i];
        g_partials[bid] = v;
        __threadfence();
        unsigned int t = atomicInc(&g_count, NBLOCKS - 1);
        s_last = (t == NBLOCKS - 1);
    }
    __syncthreads();

    // ---- last block finishes the global reduction ----
    if (s_last) {
        __threadfence();
        float s = 0.0f;
        const volatile float* gp = g_partials;
        for (int i = tid; i < NBLOCKS; i += 256)
            s += gp[i];
        #pragma unroll
        for (int off = 16; off > 0; off >>= 1)
            s += __shfl_xor_sync(0xffffffffu, s, off);
        if (lane == 0) ssum[warp] = s;
        __syncthreads();
        if (warp == 0) {
            float v = (lane < 8) ? ssum[lane] : 0.0f;
            #pragma unroll
            for (int off = 4; off > 0; off >>= 1)
                v += __shfl_xor_sync(0xffffffffu, v, off);
            if (lane == 0)
                out[0] = v * (1.0f / (float)NELEM);
        }
    }
}

extern "C" void kernel_launch(void* const* d_in, const int* in_sizes, int n_in,
                              void* d_out, int out_size) {
    const float* x1 = (const float*)d_in[0];
    const float* x2 = (const float*)d_in[1];
    float* out = (float*)d_out;
    (void)in_sizes; (void)n_in; (void)out_size;

    dim3 block(64, 4, 1);
    dim3 grid(HTILES, DCHUNKS, 1);
    grad_loss_fused<<<grid, block>>>(x1, x2, out);
}

// round 12
// speedup vs baseline: 1.3642x; 1.3642x over previous
#include <cuda_runtime.h>

#define DIM 256
#define PLANE (DIM*DIM)
#define NELEM (DIM*DIM*DIM)

#define HTILES 32          // h tiles of 8 rows (2 rows per thread)
#define DCHUNKS 17
#define DPC 15             // 17*15 = 255 >= 254; 544 blocks ~ one occ-4 wave
#define NBLOCKS (HTILES*DCHUNKS)   // 544

__device__ float g_partials[NBLOCKS];
__device__ unsigned int g_count = 0;   // wraps to 0 each launch via atomicInc

__device__ __forceinline__ float sqrt_approx(float x) {
    float r;
    asm("sqrt.approx.f32 %0, %1;" : "=f"(r) : "f"(x));
    return r;
}

__global__ __launch_bounds__(256, 4)
void grad_loss_fused(const float* __restrict__ x1,
                     const float* __restrict__ x2,
                     float* __restrict__ out) {
    __shared__ float ssum[8];
    __shared__ int s_last;

    const int tx = threadIdx.x;            // 0..63 -> w quad
    const int ty = threadIdx.y;            // 0..3  -> row pair
    const int htile = blockIdx.x;          // 0..31
    const int chunk = blockIdx.y;          // 0..16
    const int bid = chunk * HTILES + htile;

    const int h  = 1 + htile * 8 + ty * 2; // odd, 1..255
    const int h2 = h + 1;                  // even, 2..256
    const int w0 = tx * 4;
    const int d0 = 1 + chunk * DPC;
    const int niter = min(DIM - 2, d0 + DPC - 1) - d0 + 1;  // 15 (last: 14)

    const bool hcomp = (h2 <= DIM - 2);    // h odd => covers both rows

    float local = 0.0f;

    if (hcomp) {
        const float wh1 = (h  == 1)       ? 2.0f : 1.0f;
        const float wh2 = (h2 == DIM - 2) ? 2.0f : 1.0f;
        const float wl  = (tx == 0)  ? 2.0f : 1.0f;
        const float wr  = (tx == 63) ? 2.0f : 1.0f;
        const bool  hasl = (tx > 0);
        const bool  hasr = (tx < 63);

        // q points at (d, h, w0); row h2 = +DIM. Advance by PLANE per iter.
        const float* q1 = x1 + d0 * PLANE + h * DIM + w0;
        const float* q2 = x2 + d0 * PLANE + h * DIM + w0;

        // Register window (2 rows x 2 inputs): B = plane d, C = plane d+1.
        // D = plane d+2 prefetched one iteration ahead; A = plane d-1 and
        // the up/dn boundary rows are cache re-reads.
        float4 B0a = *(const float4*)(q1);
        float4 B0b = *(const float4*)(q1 + DIM);
        float4 B1a = *(const float4*)(q2);
        float4 B1b = *(const float4*)(q2 + DIM);
        float4 C0a = *(const float4*)(q1 + PLANE);
        float4 C0b = *(const float4*)(q1 + PLANE + DIM);
        float4 C1a = *(const float4*)(q2 + PLANE);
        float4 C1b = *(const float4*)(q2 + PLANE + DIM);

        int d = d0;
        #pragma unroll 1
        for (int it = 0; it < niter; ++it, ++d, q1 += PLANE, q2 += PLANE) {
            // ---- prefetch plane d+2 (consumed NEXT iteration) ----
            const int pf = (d + 2 <= DIM - 1) ? 2 * PLANE : PLANE;
            const float4 D0a = *(const float4*)(q1 + pf);
            const float4 D0b = *(const float4*)(q1 + pf + DIM);
            const float4 D1a = *(const float4*)(q2 + pf);
            const float4 D1b = *(const float4*)(q2 + pf + DIM);

            const float wd = (d == 1 || d == DIM - 2) ? 2.0f : 1.0f;
            float gw, gh, gd;

            // ================= input 0 =================
            float m0a0, m0a1, m0a2, m0a3, m0b0, m0b1, m0b2, m0b3;
            {
                const float4 A0a = *(const float4*)(q1 - PLANE);
                const float4 A0b = *(const float4*)(q1 - PLANE + DIM);
                const float4 up0 = *(const float4*)(q1 - DIM);       // row h-1
                const float4 dn0 = *(const float4*)(q1 + 2 * DIM);   // row h+2
                const float lfa = hasl ? q1[-1]      : 0.0f;
                const float rta = hasr ? q1[4]       : 0.0f;
                const float lfb = hasl ? q1[DIM - 1] : 0.0f;
                const float rtb = hasr ? q1[DIM + 4] : 0.0f;

                // row h: gh = B0b - up0, gd = C0a - A0a
                gw = B0a.y - lfa;   gh = B0b.x - up0.x;  gd = C0a.x - A0a.x;
                m0a0 = sqrt_approx(gw*gw + gh*gh + gd*gd + 1e-6f);
                gw = B0a.z - B0a.x; gh = B0b.y - up0.y;  gd = C0a.y - A0a.y;
                m0a1 = sqrt_approx(gw*gw + gh*gh + gd*gd + 1e-6f);
                gw = B0a.w - B0a.y; gh = B0b.z - up0.z;  gd = C0a.z - A0a.z;
                m0a2 = sqrt_approx(gw*gw + gh*gh + gd*gd + 1e-6f);
                gw = rta - B0a.z;   gh = B0b.w - up0.w;  gd = C0a.w - A0a.w;
                m0a3 = sqrt_approx(gw*gw + gh*gh + gd*gd + 1e-6f);

                // row h2: gh = dn0 - B0a, gd = C0b - A0b
                gw = B0b.y - lfb;   gh = dn0.x - B0a.x;  gd = C0b.x - A0b.x;
                m0b0 = sqrt_approx(gw*gw + gh*gh + gd*gd + 1e-6f);
                gw = B0b.z - B0b.x; gh = dn0.y - B0a.y;  gd = C0b.y - A0b.y;
                m0b1 = sqrt_approx(gw*gw + gh*gh + gd*gd + 1e-6f);
                gw = B0b.w - B0b.y; gh = dn0.z - B0a.z;  gd = C0b.z - A0b.z;
                m0b2 = sqrt_approx(gw*gw + gh*gh + gd*gd + 1e-6f);
                gw = rtb - B0b.z;   gh = dn0.w - B0a.w;  gd = C0b.w - A0b.w;
                m0b3 = sqrt_approx(gw*gw + gh*gh + gd*gd + 1e-6f);
            }

            // ================= input 1 =================
            float sa = 0.0f, sb = 0.0f;
            {
                const float4 A1a = *(const float4*)(q2 - PLANE);
                const float4 A1b = *(const float4*)(q2 - PLANE + DIM);
                const float4 up1 = *(const float4*)(q2 - DIM);
                const float4 dn1 = *(const float4*)(q2 + 2 * DIM);
                const float lfa = hasl ? q2[-1]      : 0.0f;
                const float rta = hasr ? q2[4]       : 0.0f;
                const float lfb = hasl ? q2[DIM - 1] : 0.0f;
                const float rtb = hasr ? q2[DIM + 4] : 0.0f;

                float m;
                gw = B1a.y - lfa;   gh = B1b.x - up1.x;  gd = C1a.x - A1a.x;
                m = sqrt_approx(gw*gw + gh*gh + gd*gd + 1e-6f);
                if (hasl) sa += fabsf(m0a0 - m);
                gw = B1a.z - B1a.x; gh = B1b.y - up1.y;  gd = C1a.y - A1a.y;
                m = sqrt_approx(gw*gw + gh*gh + gd*gd + 1e-6f);
                sa += wl * fabsf(m0a1 - m);
                gw = B1a.w - B1a.y; gh = B1b.z - up1.z;  gd = C1a.z - A1a.z;
                m = sqrt_approx(gw*gw + gh*gh + gd*gd + 1e-6f);
                sa += wr * fabsf(m0a2 - m);
                gw = rta - B1a.z;   gh = B1b.w - up1.w;  gd = C1a.w - A1a.w;
                m = sqrt_approx(gw*gw + gh*gh + gd*gd + 1e-6f);
                if (hasr) sa += fabsf(m0a3 - m);

                gw = B1b.y - lfb;   gh = dn1.x - B1a.x;  gd = C1b.x - A1b.x;
                m = sqrt_approx(gw*gw + gh*gh + gd*gd + 1e-6f);
                if (hasl) sb += fabsf(m0b0 - m);
                gw = B1b.z - B1b.x; gh = dn1.y - B1a.y;  gd = C1b.y - A1b.y;
                m = sqrt_approx(gw*gw + gh*gh + gd*gd + 1e-6f);
                sb += wl * fabsf(m0b1 - m);
                gw = B1b.w - B1b.y; gh = dn1.z - B1a.z;  gd = C1b.z - A1b.z;
                m = sqrt_approx(gw*gw + gh*gh + gd*gd + 1e-6f);
                sb += wr * fabsf(m0b2 - m);
                gw = rtb - B1b.z;   gh = dn1.w - B1a.w;  gd = C1b.w - A1b.w;
                m = sqrt_approx(gw*gw + gh*gh + gd*gd + 1e-6f);
                if (hasr) sb += fabsf(m0b3 - m);
            }

            local += wd * (wh1 * sa + wh2 * sb);

            // rotate window forward
            B0a = C0a; B0b = C0b; B1a = C1a; B1b = C1b;
            C0a = D0a; C0b = D0b; C1a = D1a; C1b = D1b;
        }
    }

    // ---- block reduction ----
    #pragma unroll
    for (int off = 16; off > 0; off >>= 1)
        local += __shfl_xor_sync(0xffffffffu, local, off);

    const int tid  = ty * 64 + tx;
    const int warp = tid >> 5;
    const int lane = tid & 31;
    if (lane == 0) ssum[warp] = local;
    __syncthreads();

    if (tid == 0) {
        float v = 0.0f;
        #pragma unroll
        for (int i = 0; i < 8; ++i) v += ssum[i];
        g_partials[bid] = v;
        __threadfence();
        unsigned int t = atomicInc(&g_count, NBLOCKS - 1);
        s_last = (t == NBLOCKS - 1);
    }
    __syncthreads();

    // ---- last block finishes the global reduction ----
    if (s_last) {
        __threadfence();
        float s = 0.0f;
        const volatile float* gp = g_partials;
        for (int i = tid; i < NBLOCKS; i += 256)
            s += gp[i];
        #pragma unroll
        for (int off = 16; off > 0; off >>= 1)
            s += __shfl_xor_sync(0xffffffffu, s, off);
        if (lane == 0) ssum[warp] = s;
        __syncthreads();
        if (warp == 0) {
            float v = (lane < 8) ? ssum[lane] : 0.0f;
            #pragma unroll
            for (int off = 4; off > 0; off >>= 1)
                v += __shfl_xor_sync(0xffffffffu, v, off);
            if (lane == 0)
                out[0] = v * (1.0f / (float)NELEM);
        }
    }
}

extern "C" void kernel_launch(void* const* d_in, const int* in_sizes, int n_in,
                              void* d_out, int out_size) {
    const float* x1 = (const float*)d_in[0];
    const float* x2 = (const float*)d_in[1];
    float* out = (float*)d_out;
    (void)in_sizes; (void)n_in; (void)out_size;

    dim3 block(64, 4, 1);
    dim3 grid(HTILES, DCHUNKS, 1);
    grad_loss_fused<<<grid, block>>>(x1, x2, out);
}

// round 13
// speedup vs baseline: 2.2438x; 1.6449x over previous
#include <cuda_runtime.h>

#define DIM 256
#define PLANE (DIM*DIM)
#define NELEM (DIM*DIM*DIM)

#define HTILES 64          // h tiles of 4 rows (1 row per thread)
#define DCHUNKS 9          // 7 chunks of 28 iters + 2 of 29 (balanced)
#define NBLOCKS (HTILES*DCHUNKS)   // 576 ~ one occ-4 wave (592 slots)

__device__ float g_partials[NBLOCKS];
__device__ unsigned int g_count = 0;   // wraps to 0 each launch via atomicInc

__device__ __forceinline__ float sqrt_approx(float x) {
    float r;
    asm("sqrt.approx.f32 %0, %1;" : "=f"(r) : "f"(x));
    return r;
}

__global__ __launch_bounds__(256, 4)
void grad_loss_fused(const float* __restrict__ x1,
                     const float* __restrict__ x2,
                     float* __restrict__ out) {
    __shared__ float ssum[8];
    __shared__ int s_last;

    const int tx = threadIdx.x;            // 0..63 -> w quad
    const int ty = threadIdx.y;            // 0..3  -> h row
    const int htile = blockIdx.x;          // 0..63
    const int chunk = blockIdx.y;          // 0..8
    const int bid = chunk * HTILES + htile;

    const int h  = 1 + htile * 4 + ty;     // 1..256
    const int w0 = tx * 4;
    // Balanced chunking: chunks 0,1 get 29 iters, chunks 2..8 get 28.
    const int d0    = 1 + chunk * 28 + min(chunk, 2);
    const int niter = 28 + (chunk < 2 ? 1 : 0);

    const bool hcomp = (h <= DIM - 2);     // uniform per warp

    float local = 0.0f;

    if (hcomp) {
        const float wh  = (h == 1 || h == DIM - 2) ? 2.0f : 1.0f;
        const float wl  = (tx == 0)  ? 2.0f : 1.0f;
        const float wr  = (tx == 63) ? 2.0f : 1.0f;
        const bool  hasl = (tx > 0);
        const bool  hasr = (tx < 63);

        // q points at (d, h, w0); advance by PLANE per iteration.
        const float* q1 = x1 + d0 * PLANE + h * DIM + w0;
        const float* q2 = x2 + d0 * PLANE + h * DIM + w0;

        // Register window: A = d-1, B = d, C = d+1; D = d+2 prefetched
        // one full iteration ahead of use.
        float4 A0 = *(const float4*)(q1 - PLANE);
        float4 A1 = *(const float4*)(q2 - PLANE);
        float4 B0 = *(const float4*)(q1);
        float4 B1 = *(const float4*)(q2);
        float4 C0 = *(const float4*)(q1 + PLANE);
        float4 C1 = *(const float4*)(q2 + PLANE);

        int d = d0;
        #pragma unroll 4
        for (int it = 0; it < niter; ++it, ++d, q1 += PLANE, q2 += PLANE) {
            // ---- prefetch plane d+2 (consumed NEXT iteration) ----
            const int pf = (d + 2 <= DIM - 1) ? 2 * PLANE : PLANE;
            const float4 D0 = *(const float4*)(q1 + pf);
            const float4 D1 = *(const float4*)(q2 + pf);

            // ---- cache-resident neighbor loads for this iteration ----
            const float4 up0 = *(const float4*)(q1 - DIM);
            const float4 dn0 = *(const float4*)(q1 + DIM);
            const float4 up1 = *(const float4*)(q2 - DIM);
            const float4 dn1 = *(const float4*)(q2 + DIM);
            const float lf0 = hasl ? q1[-1] : 0.0f;
            const float rt0 = hasr ? q1[4]  : 0.0f;
            const float lf1 = hasl ? q2[-1] : 0.0f;
            const float rt1 = hasr ? q2[4]  : 0.0f;

            const float wd = (d == 1 || d == DIM - 2) ? 2.0f : 1.0f;

            float gw, gh, gd;
            float m00, m01, m02, m03;
            gw = B0.y - lf0;  gh = dn0.x - up0.x;  gd = C0.x - A0.x;
            m00 = sqrt_approx(gw*gw + gh*gh + gd*gd + 1e-6f);
            gw = B0.z - B0.x; gh = dn0.y - up0.y;  gd = C0.y - A0.y;
            m01 = sqrt_approx(gw*gw + gh*gh + gd*gd + 1e-6f);
            gw = B0.w - B0.y; gh = dn0.z - up0.z;  gd = C0.z - A0.z;
            m02 = sqrt_approx(gw*gw + gh*gh + gd*gd + 1e-6f);
            gw = rt0 - B0.z;  gh = dn0.w - up0.w;  gd = C0.w - A0.w;
            m03 = sqrt_approx(gw*gw + gh*gh + gd*gd + 1e-6f);

            float m10, m11, m12, m13;
            gw = B1.y - lf1;  gh = dn1.x - up1.x;  gd = C1.x - A1.x;
            m10 = sqrt_approx(gw*gw + gh*gh + gd*gd + 1e-6f);
            gw = B1.z - B1.x; gh = dn1.y - up1.y;  gd = C1.y - A1.y;
            m11 = sqrt_approx(gw*gw + gh*gh + gd*gd + 1e-6f);
            gw = B1.w - B1.y; gh = dn1.z - up1.z;  gd = C1.z - A1.z;
            m12 = sqrt_approx(gw*gw + gh*gh + gd*gd + 1e-6f);
            gw = rt1 - B1.z;  gh = dn1.w - up1.w;  gd = C1.w - A1.w;
            m13 = sqrt_approx(gw*gw + gh*gh + gd*gd + 1e-6f);

            float s = 0.0f;
            if (hasl) s += fabsf(m00 - m10);
            s += wl * fabsf(m01 - m11);
            s += wr * fabsf(m02 - m12);
            if (hasr) s += fabsf(m03 - m13);
            local += wd * wh * s;

            // rotate window forward (renamed away by unroll 4)
            A0 = B0; A1 = B1; B0 = C0; B1 = C1; C0 = D0; C1 = D1;
        }
    }

    // ---- block reduction ----
    #pragma unroll
    for (int off = 16; off > 0; off >>= 1)
        local += __shfl_xor_sync(0xffffffffu, local, off);

    const int tid  = ty * 64 + tx;
    const int warp = tid >> 5;
    const int lane = tid & 31;
    if (lane == 0) ssum[warp] = local;
    __syncthreads();

    if (tid == 0) {
        float v = 0.0f;
        #pragma unroll
        for (int i = 0; i < 8; ++i) v += ssum[i];
        g_partials[bid] = v;
        __threadfence();
        unsigned int t = atomicInc(&g_count, NBLOCKS - 1);
        s_last = (t == NBLOCKS - 1);
    }
    __syncthreads();

    // ---- last block finishes the global reduction ----
    if (s_last) {
        __threadfence();
        float s = 0.0f;
        const volatile float* gp = g_partials;
        for (int i = tid; i < NBLOCKS; i += 256)
            s += gp[i];
        #pragma unroll
        for (int off = 16; off > 0; off >>= 1)
            s += __shfl_xor_sync(0xffffffffu, s, off);
        if (lane == 0) ssum[warp] = s;
        __syncthreads();
        if (warp == 0) {
            float v = (lane < 8) ? ssum[lane] : 0.0f;
            #pragma unroll
            for (int off = 4; off > 0; off >>= 1)
                v += __shfl_xor_sync(0xffffffffu, v, off);
            if (lane == 0)
                out[0] = v * (1.0f / (float)NELEM);
        }
    }
}

extern "C" void kernel_launch(void* const* d_in, const int* in_sizes, int n_in,
                              void* d_out, int out_size) {
    const float* x1 = (const float*)d_in[0];
    const float* x2 = (const float*)d_in[1];
    float* out = (float*)d_out;
    (void)in_sizes; (void)n_in; (void)out_size;

    dim3 block(64, 4, 1);
    dim3 grid(HTILES, DCHUNKS, 1);
    grad_loss_fused<<<grid, block>>>(x1, x2, out);
}